// round 16
// baseline (speedup 1.0000x reference)
#include <cuda_runtime.h>
#include <cstdint>

#define N     8192
#define K1    31
#define CAP   256      // per-line candidate capacity (mean 88, max ~135)
#define PIVOT 2.3f     // P(z>2.3)=0.0107 -> E[cand]=88 per line
#define NF4   ((size_t)N * N / 4)
#define FULLM 0xFFFFFFFFu

__device__ uint4              g_bits[(size_t)N * N / 128]; // 8 MB bitmask (1 rec / 128 elems)
__device__ unsigned long long g_colcand[(size_t)N * CAP];  // 16 MB
__device__ int                g_colcnt[N];
__device__ unsigned long long g_rowth[N];

// Monotone map float -> uint32 (larger float => larger key)
__device__ __forceinline__ unsigned int fkey(float x) {
    unsigned int u = __float_as_uint(x);
    return (u & 0x80000000u) ? ~u : (u | 0x80000000u);
}
__device__ __forceinline__ float inv_fkey(unsigned int k) {
    unsigned int u = (k & 0x80000000u) ? (k ^ 0x80000000u) : ~k;
    return __uint_as_float(u);
}
// Composite key: value-major, lower index wins ties (stable top_k semantics)
__device__ __forceinline__ unsigned long long ckey(float x, int idx) {
    return ((unsigned long long)fkey(x) << 32) | (unsigned int)(N - 1 - idx);
}

// block-level exact fallback: K1-th largest key of a full line (exactness
// guard for arbitrary inputs; statistically never triggered)
template <bool ROW, int BT>
__device__ unsigned long long block_fallback(const float* __restrict__ A, int line) {
    __shared__ unsigned long long red[BT];
    unsigned long long prev = 0xFFFFFFFFFFFFFFFFull;
    for (int it = 0; it < K1; it++) {
        unsigned long long best = 0;
        for (int t = threadIdx.x; t < N; t += BT) {
            float x = ROW ? A[(size_t)line * N + t] : A[(size_t)t * N + line];
            unsigned long long k = ckey(x, t);
            if (k < prev && k > best) best = k;
        }
        red[threadIdx.x] = best;
        __syncthreads();
        for (int s = BT / 2; s > 0; s >>= 1) {
            if (threadIdx.x < s) {
                unsigned long long o = red[threadIdx.x + s];
                if (o > red[threadIdx.x]) red[threadIdx.x] = o;
            }
            __syncthreads();
        }
        prev = red[0];
        __syncthreads();
    }
    return prev;
}

// K1: PURE streaming pass (measured 78.9-81.4us @ ~6.2TB/s). Reads A (.cs),
// zeros out (.cs), emits bitmask via ballots; first 32 blocks zero g_colcnt.
// Record gw covers elements gw*128 + lane*4 + c (word c, bit lane).
__global__ __launch_bounds__(256) void stream_kernel(const float* __restrict__ A,
                                                     float* __restrict__ out) {
    if (blockIdx.x < N / 256) g_colcnt[blockIdx.x * 256 + threadIdx.x] = 0;
    const size_t g = (size_t)blockIdx.x * 256 + threadIdx.x;  // float4 index
    float4 v = __ldcs(&((const float4*)A)[g]);
    const float4 zz = {0.0f, 0.0f, 0.0f, 0.0f};
    __stcs(&((float4*)out)[g], zz);
    unsigned m0 = __ballot_sync(FULLM, v.x > PIVOT);
    unsigned m1 = __ballot_sync(FULLM, v.y > PIVOT);
    unsigned m2 = __ballot_sync(FULLM, v.z > PIVOT);
    unsigned m3 = __ballot_sync(FULLM, v.w > PIVOT);
    if ((threadIdx.x & 31) == 0) {
        uint4 w = {m0, m1, m2, m3};
        g_bits[g >> 5] = w;
    }
}

// K2: block per row, 128 threads. Phase A: decode bit positions into smem
// (ALU only). Phase B: independent strided gather + column push. Phase C:
// rank-count rowth. No dependent memory chains.
__global__ __launch_bounds__(128) void rowth_push_kernel(const float* __restrict__ A) {
    const int i = blockIdx.x, t = threadIdx.x, lane = t & 31, w = t >> 5;
    __shared__ unsigned short idxs[CAP];
    __shared__ unsigned long long keys[CAP];
    __shared__ int wsum[2];

    uint4 b = {0, 0, 0, 0};
    int cnt = 0;
    if (t < 64) {
        b = g_bits[(size_t)i * 64 + t];
        cnt = __popc(b.x) + __popc(b.y) + __popc(b.z) + __popc(b.w);
    }
    int incl = cnt;
#pragma unroll
    for (int d = 1; d < 32; d <<= 1) {
        int vv = __shfl_up_sync(FULLM, incl, d);
        if (lane >= d) incl += vv;
    }
    if (w < 2 && lane == 31) wsum[w] = incl;
    __syncthreads();
    const int total = wsum[0] + wsum[1];
    const bool fits = (total <= CAP);
    int off = incl - cnt + ((w == 1) ? wsum[0] : 0);

    if (t < 64 && cnt) {
        unsigned words[4] = {b.x, b.y, b.z, b.w};
#pragma unroll
        for (int c = 0; c < 4; c++) {
            unsigned wb = words[c];
            while (wb) {
                int l = __ffs(wb) - 1;
                wb &= wb - 1;
                int j = t * 128 + l * 4 + c;
                if (fits) idxs[off] = (unsigned short)j;
                else {  // ultra-rare overflow: inline gather+push, list skipped
                    float x = A[(size_t)i * N + j];
                    int cs = atomicAdd(&g_colcnt[j], 1);
                    if (cs < CAP) g_colcand[(size_t)j * CAP + cs] = ckey(x, i);
                }
                off++;
            }
        }
    }
    __syncthreads();

    if (fits) {
        for (int s = t; s < total; s += 128) {
            const int j = idxs[s];
            const float x = A[(size_t)i * N + j];   // independent load
            const unsigned long long k = ckey(x, j);
            keys[s] = k;
            const unsigned long long colk =
                (k & 0xFFFFFFFF00000000ull) | (unsigned int)(N - 1 - i);
            int cs = atomicAdd(&g_colcnt[j], 1);     // independent atomic
            if (cs < CAP) g_colcand[(size_t)j * CAP + cs] = colk;
        }
    }
    __syncthreads();

    if (fits && total >= K1) {
        for (int s = t; s < total; s += 128) {
            unsigned long long kt = keys[s];
            int r = 0;
            for (int m = 0; m < total; m++) r += (keys[m] > kt);
            if (r == K1 - 1) g_rowth[i] = kt;        // exactly one writer
        }
    } else {
        unsigned long long th = block_fallback<true, 128>(A, i);
        if (t == 0) g_rowth[i] = th;
    }
}

// K3: block per column (128 thr). colth by rank-counting the list, then
// scatter survivors. Healthy columns: every survivor is > PIVOT and in the
// list. Unhealthy (under/overflow): exact threshold + full-column rescan.
__global__ __launch_bounds__(128) void colth_scatter_kernel(const float* __restrict__ A,
                                                            float* __restrict__ out) {
    const int j = blockIdx.x, t = threadIdx.x;
    const int c = __ldg(&g_colcnt[j]);
    __shared__ unsigned long long cand[CAP];
    __shared__ unsigned long long s_cth;

    if (c >= K1 && c <= CAP) {
        for (int s = t; s < c; s += 128)
            cand[s] = g_colcand[(size_t)j * CAP + s];
        __syncthreads();
        for (int s = t; s < c; s += 128) {
            unsigned long long kt = cand[s];
            int r = 0;
            for (int m = 0; m < c; m++) r += (cand[m] > kt);
            if (r == K1 - 1) s_cth = kt;
        }
        __syncthreads();
        const unsigned long long cth = s_cth;
        for (int s = t; s < c; s += 128) {
            unsigned long long k = cand[s];
            if (k < cth) continue;
            int i = N - 1 - (int)(unsigned int)(k & 0xFFFFFFFFu);
            if (i == j) continue;
            float x = inv_fkey((unsigned int)(k >> 32));
            if (ckey(x, j) >= g_rowth[i])
                out[(size_t)i * N + j] = x;
        }
    } else {
        unsigned long long cth = block_fallback<false, 128>(A, j);
        for (int i = t; i < N; i += 128) {
            if (i == j) continue;
            float x = A[(size_t)i * N + j];
            if (ckey(x, i) >= cth && ckey(x, j) >= g_rowth[i])
                out[(size_t)i * N + j] = x;
        }
    }
}

extern "C" void kernel_launch(void* const* d_in, const int* in_sizes, int n_in,
                              void* d_out, int out_size) {
    const float* A = (const float*)d_in[0];
    float* out = (float*)d_out;
    stream_kernel<<<(unsigned)(NF4 / 256), 256>>>(A, out);
    rowth_push_kernel<<<N, 128>>>(A);
    colth_scatter_kernel<<<N, 128>>>(A, out);
}